// round 7
// baseline (speedup 1.0000x reference)
#include <cuda_runtime.h>

// Problem constants (fixed by the dataset)
#define B_   128
#define E_   100000
#define F_   5000
#define C_   8
#define DIN_ 10
#define DOUT_ 10
#define H_   (F_ * C_)
#define EPS_ 1e-5f

#define NCTA 1000   // persistent grid: all co-resident (<=7 CTAs/SM needed)
#define FPC  5      // function nodes per CTA (NCTA * FPC == F_)

// Scratch (static device mem): single transposed array.
__device__ float g_outT[(size_t)E_ * B_];          // outT[e][b] = x + b3 -> += scatter
__device__ unsigned long long g_bar = 0ULL;        // monotonic grid barrier ticket

// ---------------------------------------------------------------------------
// Kernel A: vectorized tiled transpose: outT[e][b] = x[b][e] + b3[e]
// ---------------------------------------------------------------------------
__global__ __launch_bounds__(256)
void transpose_init_kernel(const float* __restrict__ x,
                           const float* __restrict__ b3) {
    __shared__ float tile[32][33];            // tile[e_loc][b_loc]
    const int e0 = blockIdx.x * 32;
    const int b0 = blockIdx.y * 32;
    const int tx = threadIdx.x;               // 0..7  (float4 index)
    const int ty = threadIdx.y;               // 0..31

    {
        const int b = b0 + ty;
        float4 v = __ldcs(reinterpret_cast<const float4*>(
                              x + (size_t)b * E_ + e0) + tx);
        tile[tx * 4 + 0][ty] = v.x;
        tile[tx * 4 + 1][ty] = v.y;
        tile[tx * 4 + 2][ty] = v.z;
        tile[tx * 4 + 3][ty] = v.w;
    }
    __syncthreads();
    {
        const int e = e0 + ty;
        const float bias = __ldg(b3 + e);
        float4 w;
        w.x = tile[ty][tx * 4 + 0] + bias;
        w.y = tile[ty][tx * 4 + 1] + bias;
        w.z = tile[ty][tx * 4 + 2] + bias;
        w.w = tile[ty][tx * 4 + 3] + bias;
        reinterpret_cast<float4*>(&g_outT[(size_t)e * B_ + b0])[tx] = w;
    }
}

// ---------------------------------------------------------------------------
// Kernel D: vectorized tiled transpose outT[e][b] -> out[b][e]
// ---------------------------------------------------------------------------
__global__ __launch_bounds__(256)
void transpose_out_kernel(float* __restrict__ out) {
    __shared__ float tile[32][33];            // tile[b_loc][e_loc]
    const int e0 = blockIdx.x * 32;
    const int b0 = blockIdx.y * 32;
    const int tx = threadIdx.x;
    const int ty = threadIdx.y;

    {
        const int e = e0 + ty;
        float4 v = reinterpret_cast<const float4*>(
                       &g_outT[(size_t)e * B_ + b0])[tx];
        tile[tx * 4 + 0][ty] = v.x;
        tile[tx * 4 + 1][ty] = v.y;
        tile[tx * 4 + 2][ty] = v.z;
        tile[tx * 4 + 3][ty] = v.w;
    }
    __syncthreads();
    {
        const int b = b0 + ty;
        float4 w;
        w.x = tile[ty][tx * 4 + 0];
        w.y = tile[ty][tx * 4 + 1];
        w.z = tile[ty][tx * 4 + 2];
        w.w = tile[ty][tx * 4 + 3];
        __stcs(reinterpret_cast<float4*>(out + (size_t)b * E_ + e0) + tx, w);
    }
}

__device__ __forceinline__ float elu1(float z) {
    return z > 0.0f ? z : expm1f(z);
}

// ---------------------------------------------------------------------------
// Kernel C: persistent fused gather->MLP->scatter with software grid barrier.
// 1000 CTAs x 128 threads; each CTA handles 5 function nodes. Phase 1 gathers
// x = outT - b3 and parks h in smem; ticket barrier; phase 2 scatters into outT.
// ---------------------------------------------------------------------------
__global__ __launch_bounds__(B_)
void fused_fn_kernel(const float* __restrict__ s,
                     const float* __restrict__ w1,
                     const float* __restrict__ b1,
                     const float* __restrict__ w2,
                     const float* __restrict__ b2,
                     const float* __restrict__ w3,
                     const float* __restrict__ b3,
                     const int*   __restrict__ src1,  // in_e[f,d] = src1[(f*10+d)*8]
                     const int*   __restrict__ dst3,  // out_e[f,d] = dst3[(f*10+d)*8]
                     const float* __restrict__ g1,
                     const float* __restrict__ bt1,
                     const float* __restrict__ g2,
                     const float* __restrict__ bt2) {
    __shared__ float hstore[FPC][C_][B_];            // 20.5 KB
    __shared__ float w1s[DIN_ * C_];
    __shared__ float w2s[C_ * C_];
    __shared__ float w3s[DOUT_ * C_];
    __shared__ int   ine[DIN_];
    __shared__ int   oute[DOUT_];
    __shared__ float b3g[DIN_];
    __shared__ float b1s[C_], b2s[C_], g1s[C_], bt1s[C_], g2s[C_], bt2s[C_];

    const int tid = threadIdx.x;                     // == batch index b
    const int b   = tid;

    // ================= Phase 1: gather + MLP =================
    for (int i = 0; i < FPC; i++) {
        const int f = blockIdx.x * FPC + i;

        __syncthreads();   // protect param buffers from previous iteration
        if (tid < DIN_ * C_)  w1s[tid] = w1[f * (DIN_ * C_) + tid];
        if (tid < C_ * C_)    w2s[tid] = w2[f * (C_ * C_) + tid];
        if (tid < DIN_) {
            int e = src1[(f * DIN_ + tid) * C_];
            ine[tid] = e;
            b3g[tid] = __ldg(b3 + e);
        }
        if (tid < C_) {
            int hc = f * C_ + tid;
            b1s[tid]  = b1[hc];
            b2s[tid]  = b2[hc];
            g1s[tid]  = g1[hc];
            bt1s[tid] = bt1[hc];
            g2s[tid]  = g2[hc];
            bt2s[tid] = bt2[hc];
        }
        __syncthreads();

        // gather x = outT - b3 (coalesced, MLP=10)
        float xv[DIN_];
#pragma unroll
        for (int d = 0; d < DIN_; d++)
            xv[d] = __ldg(&g_outT[(size_t)ine[d] * B_ + b]) - b3g[d];

        // s[b, f*8..f*8+7]
        const float4* srow = reinterpret_cast<const float4*>(
                                 s + (size_t)b * H_ + f * C_);
        float4 sa = srow[0], sb = srow[1];
        float sv[C_] = {sa.x, sa.y, sa.z, sa.w, sb.x, sb.y, sb.z, sb.w};

        // w1: 10x8 dense
        float h[C_];
#pragma unroll
        for (int c = 0; c < C_; c++) {
            float acc = b1s[c];
#pragma unroll
            for (int d = 0; d < DIN_; d++) acc = fmaf(xv[d], w1s[d * C_ + c], acc);
            h[c] = acc;
        }

        // groupLN 1 + affine + elu(s*h)
        {
            float sum = 0.f, sq = 0.f;
#pragma unroll
            for (int c = 0; c < C_; c++) { sum += h[c]; sq += h[c] * h[c]; }
            float mu  = sum * 0.125f;
            float var = sq * 0.125f - mu * mu;
            float inv = rsqrtf(var + EPS_);
#pragma unroll
            for (int c = 0; c < C_; c++) {
                float z = (g1s[c] * ((h[c] - mu) * inv) + bt1s[c]) * sv[c];
                h[c] = elu1(z);
            }
        }

        // w2: 8x8 dense block
        float h2[C_];
#pragma unroll
        for (int c2 = 0; c2 < C_; c2++) {
            float acc = b2s[c2];
#pragma unroll
            for (int c = 0; c < C_; c++) acc = fmaf(h[c], w2s[c * C_ + c2], acc);
            h2[c2] = acc;
        }

        // groupLN 2 + affine + elu(h*s)
        {
            float sum = 0.f, sq = 0.f;
#pragma unroll
            for (int c = 0; c < C_; c++) { sum += h2[c]; sq += h2[c] * h2[c]; }
            float mu  = sum * 0.125f;
            float var = sq * 0.125f - mu * mu;
            float inv = rsqrtf(var + EPS_);
#pragma unroll
            for (int c = 0; c < C_; c++) {
                float z = (g2s[c] * ((h2[c] - mu) * inv) + bt2s[c]) * sv[c];
                hstore[i][c][b] = elu1(z);
            }
        }
    }

    // ================= Grid barrier (monotonic ticket; replay-safe) ==========
    __threadfence();
    __syncthreads();
    if (tid == 0) {
        unsigned long long ticket = atomicAdd(&g_bar, 1ULL);
        unsigned long long target = (ticket / NCTA + 1ULL) * NCTA;
        while (true) {
            unsigned long long v;
            asm volatile("ld.volatile.global.u64 %0, [%1];"
                         : "=l"(v) : "l"(&g_bar) : "memory");
            if (v >= target) break;
            __nanosleep(128);
        }
    }
    __syncthreads();

    // ================= Phase 2: w3 projection + scatter =================
    for (int i = 0; i < FPC; i++) {
        const int f = blockIdx.x * FPC + i;

        __syncthreads();
        if (tid < DOUT_ * C_) w3s[tid] = w3[f * (DOUT_ * C_) + tid];
        if (tid < DOUT_)      oute[tid] = dst3[(f * DOUT_ + tid) * C_];
        __syncthreads();

        float hv[C_];
#pragma unroll
        for (int c = 0; c < C_; c++) hv[c] = hstore[i][c][b];

#pragma unroll
        for (int d = 0; d < DOUT_; d++) {
            float acc = 0.f;
#pragma unroll
            for (int c = 0; c < C_; c++) acc = fmaf(hv[c], w3s[d * C_ + c], acc);
            atomicAdd(&g_outT[(size_t)oute[d] * B_ + b], acc);
        }
    }
}

// ---------------------------------------------------------------------------
// Launch
// ---------------------------------------------------------------------------
extern "C" void kernel_launch(void* const* d_in, const int* in_sizes, int n_in,
                              void* d_out, int out_size) {
    const float* x   = (const float*)d_in[0];
    const float* s   = (const float*)d_in[1];
    const float* w1  = (const float*)d_in[2];
    const float* b1  = (const float*)d_in[3];
    const float* w2  = (const float*)d_in[4];
    const float* b2  = (const float*)d_in[5];
    const float* w3  = (const float*)d_in[6];
    const float* b3  = (const float*)d_in[7];
    const float* g1  = (const float*)d_in[8];
    const float* bt1 = (const float*)d_in[9];
    const float* g2  = (const float*)d_in[10];
    const float* bt2 = (const float*)d_in[11];
    const int*   src1 = (const int*)d_in[12];
    const int*   dst3 = (const int*)d_in[17];
    float* out = (float*)d_out;

    dim3 tblk(8, 32);
    dim3 tgrid(E_ / 32, B_ / 32);
    transpose_init_kernel<<<tgrid, tblk>>>(x, b3);
    fused_fn_kernel<<<NCTA, B_>>>(s, w1, b1, w2, b2, w3, b3,
                                  src1, dst3, g1, bt1, g2, bt2);
    transpose_out_kernel<<<tgrid, tblk>>>(out);
}

// round 8
// speedup vs baseline: 1.1169x; 1.1169x over previous
#include <cuda_runtime.h>

// Problem constants (fixed by the dataset)
#define B_   128
#define E_   100000
#define F_   5000
#define C_   8
#define DIN_ 10
#define DOUT_ 10
#define H_   (F_ * C_)
#define EPS_ 1e-5f

// Transposed scratch (static device mem). Together 102.4 MB -> fits 126 MB L2.
__device__ float g_xT[(size_t)E_ * B_];    // xT[e][b]
__device__ float g_outT[(size_t)E_ * B_];  // outT[e][b] = x + b3, scatter target

// ---------------------------------------------------------------------------
// Kernel A: high-MLP tiled transpose. Block (8,32) handles a 32e x 128b tile:
// 4 float4 loads + 8 float4 stores per thread, all independent (MLP=4/8).
// Smem padded to 129 floats/row -> conflict-free in both phases.
// ---------------------------------------------------------------------------
__global__ __launch_bounds__(256)
void transpose_init_kernel(const float* __restrict__ x,
                           const float* __restrict__ b3) {
    __shared__ float tile[32][129];           // tile[e_loc][b]
    const int e0 = blockIdx.x * 32;
    const int tx = threadIdx.x;               // 0..7
    const int ty = threadIdx.y;               // 0..31

    // Load: 4 rows of b (ty+32j), float4 at e0+4tx. Coalesced; MLP=4.
#pragma unroll
    for (int j = 0; j < 4; j++) {
        const int b = ty + 32 * j;
        float4 v = __ldcs(reinterpret_cast<const float4*>(
                              x + (size_t)b * E_ + e0) + tx);
        tile[tx * 4 + 0][b] = v.x;
        tile[tx * 4 + 1][b] = v.y;
        tile[tx * 4 + 2][b] = v.z;
        tile[tx * 4 + 3][b] = v.w;
    }
    __syncthreads();

    // Store: row e = e0+ty, 4 float4 chunks of b. Coalesced; MLP=8.
    {
        const int e = e0 + ty;
        const float bias = __ldg(b3 + e);
        const size_t row = (size_t)e * B_;
#pragma unroll
        for (int j = 0; j < 4; j++) {
            const int bb = 4 * (tx + 8 * j);
            float4 w;
            w.x = tile[ty][bb + 0];
            w.y = tile[ty][bb + 1];
            w.z = tile[ty][bb + 2];
            w.w = tile[ty][bb + 3];
            *reinterpret_cast<float4*>(&g_xT[row + bb]) = w;
            float4 w2;
            w2.x = w.x + bias; w2.y = w.y + bias;
            w2.z = w.z + bias; w2.w = w.w + bias;
            *reinterpret_cast<float4*>(&g_outT[row + bb]) = w2;
        }
    }
}

// ---------------------------------------------------------------------------
// Kernel D: high-MLP tiled transpose outT[e][b] -> out[b][e]. Same tiling.
// ---------------------------------------------------------------------------
__global__ __launch_bounds__(256)
void transpose_out_kernel(float* __restrict__ out) {
    __shared__ float tile[32][129];           // tile[e_loc][b]
    const int e0 = blockIdx.x * 32;
    const int tx = threadIdx.x;               // 0..7
    const int ty = threadIdx.y;               // 0..31

    // Load: row e = e0+ty, 4 float4 chunks of b. MLP=4.
    {
        const int e = e0 + ty;
        const size_t row = (size_t)e * B_;
#pragma unroll
        for (int j = 0; j < 4; j++) {
            const int bb = 4 * (tx + 8 * j);
            float4 v = *reinterpret_cast<const float4*>(&g_outT[row + bb]);
            tile[ty][bb + 0] = v.x;
            tile[ty][bb + 1] = v.y;
            tile[ty][bb + 2] = v.z;
            tile[ty][bb + 3] = v.w;
        }
    }
    __syncthreads();

    // Store: 4 rows of b (ty+32j), float4 at e0+4tx. Streaming; MLP=4.
#pragma unroll
    for (int j = 0; j < 4; j++) {
        const int b = ty + 32 * j;
        float4 w;
        w.x = tile[tx * 4 + 0][b];
        w.y = tile[tx * 4 + 1][b];
        w.z = tile[tx * 4 + 2][b];
        w.w = tile[tx * 4 + 3][b];
        __stcs(reinterpret_cast<float4*>(out + (size_t)b * E_ + e0) + tx, w);
    }
}

__device__ __forceinline__ float elu1(float z) {
    return z > 0.0f ? z : expm1f(z);
}

// ---------------------------------------------------------------------------
// Kernel C (exact R2/R6 config — proven best): one block per function node f,
// one thread per batch b. Natural register allocation, scalar coalesced atomics.
// ---------------------------------------------------------------------------
__global__ __launch_bounds__(B_)
void fn_node_kernel(const float* __restrict__ s,
                    const float* __restrict__ w1,
                    const float* __restrict__ b1,
                    const float* __restrict__ w2,
                    const float* __restrict__ b2,
                    const float* __restrict__ w3,
                    const int*   __restrict__ src1,   // in_e[f,d] = src1[(f*10+d)*8]
                    const int*   __restrict__ dst3,   // out_e[f,d] = dst3[(f*10+d)*8]
                    const float* __restrict__ g1,
                    const float* __restrict__ bt1,
                    const float* __restrict__ g2,
                    const float* __restrict__ bt2) {
    __shared__ float w1s[DIN_ * C_];
    __shared__ float w2s[C_ * C_];
    __shared__ float w3s[DOUT_ * C_];
    __shared__ int   ine[DIN_];
    __shared__ int   oute[DOUT_];
    __shared__ float b1s[C_], b2s[C_], g1s[C_], bt1s[C_], g2s[C_], bt2s[C_];

    const int f   = blockIdx.x;
    const int tid = threadIdx.x;   // == batch index b

    if (tid < DIN_ * C_)  w1s[tid] = w1[f * (DIN_ * C_) + tid];
    if (tid < C_ * C_)    w2s[tid] = w2[f * (C_ * C_) + tid];
    if (tid < DOUT_ * C_) w3s[tid] = w3[f * (DOUT_ * C_) + tid];
    if (tid < DIN_)       ine[tid]  = src1[(f * DIN_ + tid) * C_];
    if (tid < DOUT_)      oute[tid] = dst3[(f * DOUT_ + tid) * C_];
    if (tid < C_) {
        int hc = f * C_ + tid;
        b1s[tid]  = b1[hc];
        b2s[tid]  = b2[hc];
        g1s[tid]  = g1[hc];
        bt1s[tid] = bt1[hc];
        g2s[tid]  = g2[hc];
        bt2s[tid] = bt2[hc];
    }
    __syncthreads();

    const int b = tid;

    // ---- gather from transposed x: fully coalesced, MLP=10 ----
    float xv[DIN_];
#pragma unroll
    for (int d = 0; d < DIN_; d++) xv[d] = __ldg(&g_xT[(size_t)ine[d] * B_ + b]);

    // ---- s[b, f*8..f*8+7]: one fully-used 32B sector per thread ----
    const float4* srow = reinterpret_cast<const float4*>(s + (size_t)b * H_ + f * C_);
    float4 sa = srow[0], sb = srow[1];
    float sv[C_] = {sa.x, sa.y, sa.z, sa.w, sb.x, sb.y, sb.z, sb.w};

    // ---- w1: 10x8 dense ----
    float h[C_];
#pragma unroll
    for (int c = 0; c < C_; c++) {
        float acc = b1s[c];
#pragma unroll
        for (int d = 0; d < DIN_; d++) acc = fmaf(xv[d], w1s[d * C_ + c], acc);
        h[c] = acc;
    }

    // ---- groupLN 1 + affine + elu(s*h) ----
    {
        float sum = 0.f, sq = 0.f;
#pragma unroll
        for (int c = 0; c < C_; c++) { sum += h[c]; sq += h[c] * h[c]; }
        float mu  = sum * 0.125f;
        float var = sq * 0.125f - mu * mu;
        float inv = rsqrtf(var + EPS_);
#pragma unroll
        for (int c = 0; c < C_; c++) {
            float z = (g1s[c] * ((h[c] - mu) * inv) + bt1s[c]) * sv[c];
            h[c] = elu1(z);
        }
    }

    // ---- w2: 8x8 dense block ----
    float h2[C_];
#pragma unroll
    for (int c2 = 0; c2 < C_; c2++) {
        float acc = b2s[c2];
#pragma unroll
        for (int c = 0; c < C_; c++) acc = fmaf(h[c], w2s[c * C_ + c2], acc);
        h2[c2] = acc;
    }

    // ---- groupLN 2 + affine + elu(h*s) ----
    {
        float sum = 0.f, sq = 0.f;
#pragma unroll
        for (int c = 0; c < C_; c++) { sum += h2[c]; sq += h2[c] * h2[c]; }
        float mu  = sum * 0.125f;
        float var = sq * 0.125f - mu * mu;
        float inv = rsqrtf(var + EPS_);
#pragma unroll
        for (int c = 0; c < C_; c++) {
            float z = (g2s[c] * ((h2[c] - mu) * inv) + bt2s[c]) * sv[c];
            h[c] = elu1(z);
        }
    }

    // ---- w3: 8 -> 10 scatter, coalesced atomics into transposed out ----
#pragma unroll
    for (int d = 0; d < DOUT_; d++) {
        float acc = 0.f;
#pragma unroll
        for (int c = 0; c < C_; c++) acc = fmaf(h[c], w3s[d * C_ + c], acc);
        atomicAdd(&g_outT[(size_t)oute[d] * B_ + b], acc);
    }
}

// ---------------------------------------------------------------------------
// Launch
// ---------------------------------------------------------------------------
extern "C" void kernel_launch(void* const* d_in, const int* in_sizes, int n_in,
                              void* d_out, int out_size) {
    const float* x   = (const float*)d_in[0];
    const float* s   = (const float*)d_in[1];
    const float* w1  = (const float*)d_in[2];
    const float* b1  = (const float*)d_in[3];
    const float* w2  = (const float*)d_in[4];
    const float* b2  = (const float*)d_in[5];
    const float* w3  = (const float*)d_in[6];
    const float* b3  = (const float*)d_in[7];
    const float* g1  = (const float*)d_in[8];
    const float* bt1 = (const float*)d_in[9];
    const float* g2  = (const float*)d_in[10];
    const float* bt2 = (const float*)d_in[11];
    const int*   src1 = (const int*)d_in[12];
    const int*   dst3 = (const int*)d_in[17];
    float* out = (float*)d_out;

    dim3 tblk(8, 32);
    dim3 tgrid(E_ / 32, 1);   // each block covers 32 e x all 128 b
    transpose_init_kernel<<<tgrid, tblk>>>(x, b3);
    fn_node_kernel<<<F_, B_>>>(s, w1, b1, w2, b2, w3,
                               src1, dst3, g1, bt1, g2, bt2);
    transpose_out_kernel<<<tgrid, tblk>>>(out);
}

// round 9
// speedup vs baseline: 1.1905x; 1.0659x over previous
#include <cuda_runtime.h>

// Problem constants (fixed by the dataset)
#define B_   128
#define E_   100000
#define F_   5000
#define C_   8
#define DIN_ 10
#define DOUT_ 10
#define H_   (F_ * C_)
#define EPS_ 1e-5f

// Transposed scratch (static device mem). Together 102.4 MB -> fits 126 MB L2.
__device__ float g_xT[(size_t)E_ * B_];    // xT[e][b]
__device__ float g_outT[(size_t)E_ * B_];  // outT[e][b] = x + b3, scatter target

// ---------------------------------------------------------------------------
// Kernel A: high-MLP tiled transpose. Block (8,32) handles a 32e x 128b tile.
// ---------------------------------------------------------------------------
__global__ __launch_bounds__(256)
void transpose_init_kernel(const float* __restrict__ x,
                           const float* __restrict__ b3) {
    __shared__ float tile[32][129];           // tile[e_loc][b]
    const int e0 = blockIdx.x * 32;
    const int tx = threadIdx.x;               // 0..7
    const int ty = threadIdx.y;               // 0..31

#pragma unroll
    for (int j = 0; j < 4; j++) {
        const int b = ty + 32 * j;
        float4 v = __ldcs(reinterpret_cast<const float4*>(
                              x + (size_t)b * E_ + e0) + tx);
        tile[tx * 4 + 0][b] = v.x;
        tile[tx * 4 + 1][b] = v.y;
        tile[tx * 4 + 2][b] = v.z;
        tile[tx * 4 + 3][b] = v.w;
    }
    __syncthreads();
    {
        const int e = e0 + ty;
        const float bias = __ldg(b3 + e);
        const size_t row = (size_t)e * B_;
#pragma unroll
        for (int j = 0; j < 4; j++) {
            const int bb = 4 * (tx + 8 * j);
            float4 w;
            w.x = tile[ty][bb + 0];
            w.y = tile[ty][bb + 1];
            w.z = tile[ty][bb + 2];
            w.w = tile[ty][bb + 3];
            *reinterpret_cast<float4*>(&g_xT[row + bb]) = w;
            float4 w2;
            w2.x = w.x + bias; w2.y = w.y + bias;
            w2.z = w.z + bias; w2.w = w.w + bias;
            *reinterpret_cast<float4*>(&g_outT[row + bb]) = w2;
        }
    }
}

// ---------------------------------------------------------------------------
// Kernel D: high-MLP tiled transpose outT[e][b] -> out[b][e].
// ---------------------------------------------------------------------------
__global__ __launch_bounds__(256)
void transpose_out_kernel(float* __restrict__ out) {
    __shared__ float tile[32][129];           // tile[e_loc][b]
    const int e0 = blockIdx.x * 32;
    const int tx = threadIdx.x;
    const int ty = threadIdx.y;

    {
        const int e = e0 + ty;
        const size_t row = (size_t)e * B_;
#pragma unroll
        for (int j = 0; j < 4; j++) {
            const int bb = 4 * (tx + 8 * j);
            float4 v = *reinterpret_cast<const float4*>(&g_outT[row + bb]);
            tile[ty][bb + 0] = v.x;
            tile[ty][bb + 1] = v.y;
            tile[ty][bb + 2] = v.z;
            tile[ty][bb + 3] = v.w;
        }
    }
    __syncthreads();
#pragma unroll
    for (int j = 0; j < 4; j++) {
        const int b = ty + 32 * j;
        float4 w;
        w.x = tile[tx * 4 + 0][b];
        w.y = tile[tx * 4 + 1][b];
        w.z = tile[tx * 4 + 2][b];
        w.w = tile[tx * 4 + 3][b];
        __stcs(reinterpret_cast<float4*>(out + (size_t)b * E_ + e0) + tx, w);
    }
}

// Fast ELU: __expf (MUFU.EX2-based) instead of libdevice expm1f.
// abs error near 0 is ~1e-7 — negligible vs the 1e-3 check.
__device__ __forceinline__ float elu1(float z) {
    return z > 0.0f ? z : __expf(z) - 1.0f;
}

// ---------------------------------------------------------------------------
// Kernel C: one block per function node f, one thread per batch b (128).
// s loads hoisted to kernel entry (overlap DRAM latency with prologue).
// ---------------------------------------------------------------------------
__global__ __launch_bounds__(B_)
void fn_node_kernel(const float* __restrict__ s,
                    const float* __restrict__ w1,
                    const float* __restrict__ b1,
                    const float* __restrict__ w2,
                    const float* __restrict__ b2,
                    const float* __restrict__ w3,
                    const int*   __restrict__ src1,   // in_e[f,d] = src1[(f*10+d)*8]
                    const int*   __restrict__ dst3,   // out_e[f,d] = dst3[(f*10+d)*8]
                    const float* __restrict__ g1,
                    const float* __restrict__ bt1,
                    const float* __restrict__ g2,
                    const float* __restrict__ bt2) {
    __shared__ float w1s[DIN_ * C_];
    __shared__ float w2s[C_ * C_];
    __shared__ float w3s[DOUT_ * C_];
    __shared__ int   ine[DIN_];
    __shared__ int   oute[DOUT_];
    __shared__ float b1s[C_], b2s[C_], g1s[C_], bt1s[C_], g2s[C_], bt2s[C_];

    const int f   = blockIdx.x;
    const int tid = threadIdx.x;   // == batch index b
    const int b   = tid;

    // ---- issue s loads FIRST: long DRAM latency overlaps whole prologue ----
    const float4* srow = reinterpret_cast<const float4*>(s + (size_t)b * H_ + f * C_);
    float4 sa = srow[0];
    float4 sb = srow[1];

    if (tid < DIN_ * C_)  w1s[tid] = w1[f * (DIN_ * C_) + tid];
    if (tid < C_ * C_)    w2s[tid] = w2[f * (C_ * C_) + tid];
    if (tid < DOUT_ * C_) w3s[tid] = w3[f * (DOUT_ * C_) + tid];
    if (tid < DIN_)       ine[tid]  = src1[(f * DIN_ + tid) * C_];
    if (tid < DOUT_)      oute[tid] = dst3[(f * DOUT_ + tid) * C_];
    if (tid < C_) {
        int hc = f * C_ + tid;
        b1s[tid]  = b1[hc];
        b2s[tid]  = b2[hc];
        g1s[tid]  = g1[hc];
        bt1s[tid] = bt1[hc];
        g2s[tid]  = g2[hc];
        bt2s[tid] = bt2[hc];
    }
    __syncthreads();

    // ---- gather from transposed x: fully coalesced, MLP=10 ----
    float xv[DIN_];
#pragma unroll
    for (int d = 0; d < DIN_; d++) xv[d] = __ldg(&g_xT[(size_t)ine[d] * B_ + b]);

    float sv[C_] = {sa.x, sa.y, sa.z, sa.w, sb.x, sb.y, sb.z, sb.w};

    // ---- w1: 10x8 dense ----
    float h[C_];
#pragma unroll
    for (int c = 0; c < C_; c++) {
        float acc = b1s[c];
#pragma unroll
        for (int d = 0; d < DIN_; d++) acc = fmaf(xv[d], w1s[d * C_ + c], acc);
        h[c] = acc;
    }

    // ---- groupLN 1 + affine + elu(s*h) ----
    {
        float sum = 0.f, sq = 0.f;
#pragma unroll
        for (int c = 0; c < C_; c++) { sum += h[c]; sq += h[c] * h[c]; }
        float mu  = sum * 0.125f;
        float var = sq * 0.125f - mu * mu;
        float inv = rsqrtf(var + EPS_);
#pragma unroll
        for (int c = 0; c < C_; c++) {
            float z = (g1s[c] * ((h[c] - mu) * inv) + bt1s[c]) * sv[c];
            h[c] = elu1(z);
        }
    }

    // ---- w2: 8x8 dense block ----
    float h2[C_];
#pragma unroll
    for (int c2 = 0; c2 < C_; c2++) {
        float acc = b2s[c2];
#pragma unroll
        for (int c = 0; c < C_; c++) acc = fmaf(h[c], w2s[c * C_ + c2], acc);
        h2[c2] = acc;
    }

    // ---- groupLN 2 + affine + elu(h*s) ----
    {
        float sum = 0.f, sq = 0.f;
#pragma unroll
        for (int c = 0; c < C_; c++) { sum += h2[c]; sq += h2[c] * h2[c]; }
        float mu  = sum * 0.125f;
        float var = sq * 0.125f - mu * mu;
        float inv = rsqrtf(var + EPS_);
#pragma unroll
        for (int c = 0; c < C_; c++) {
            float z = (g2s[c] * ((h2[c] - mu) * inv) + bt2s[c]) * sv[c];
            h[c] = elu1(z);
        }
    }

    // ---- w3: 8 -> 10 scatter, coalesced atomics into transposed out ----
#pragma unroll
    for (int d = 0; d < DOUT_; d++) {
        float acc = 0.f;
#pragma unroll
        for (int c = 0; c < C_; c++) acc = fmaf(h[c], w3s[d * C_ + c], acc);
        atomicAdd(&g_outT[(size_t)oute[d] * B_ + b], acc);
    }
}

// ---------------------------------------------------------------------------
// Launch
// ---------------------------------------------------------------------------
extern "C" void kernel_launch(void* const* d_in, const int* in_sizes, int n_in,
                              void* d_out, int out_size) {
    const float* x   = (const float*)d_in[0];
    const float* s   = (const float*)d_in[1];
    const float* w1  = (const float*)d_in[2];
    const float* b1  = (const float*)d_in[3];
    const float* w2  = (const float*)d_in[4];
    const float* b2  = (const float*)d_in[5];
    const float* w3  = (const float*)d_in[6];
    const float* b3  = (const float*)d_in[7];
    const float* g1  = (const float*)d_in[8];
    const float* bt1 = (const float*)d_in[9];
    const float* g2  = (const float*)d_in[10];
    const float* bt2 = (const float*)d_in[11];
    const int*   src1 = (const int*)d_in[12];
    const int*   dst3 = (const int*)d_in[17];
    float* out = (float*)d_out;

    dim3 tblk(8, 32);
    dim3 tgrid(E_ / 32, 1);   // each block covers 32 e x all 128 b
    transpose_init_kernel<<<tgrid, tblk>>>(x, b3);
    fn_node_kernel<<<F_, B_>>>(s, w1, b1, w2, b2, w3,
                               src1, dst3, g1, bt1, g2, bt2);
    transpose_out_kernel<<<tgrid, tblk>>>(out);
}